// round 9
// baseline (speedup 1.0000x reference)
#include <cuda_runtime.h>
#include <cuda_bf16.h>
#include <cstdint>
#include <math.h>

#define NB    2
#define NPTS  16384
#define MPTS  4096
#define CIN   64
#define COUT  128
#define EPSF  1e-10f

#define NSPLIT   4
#define NPART    (NPTS/NSPLIT)      // 4096
#define NCHUNKS  (NPART/128)        // 32
#define NTILES   (NPTS/128)         // 128 per batch
#define MTILES   (MPTS/128)         // 32
#define NSTAGES  (NCHUNKS*3)        // 96

#define XYZ_OFF  0
#define FEAT_OFF (NB*MPTS*3)
#define IDX_OFF  (FEAT_OFF + NB*COUT*MPTS)

// tile block: [128 rows][64 bf16 cols] SW128 image = 16384 B; split (K=128) = 2 blocks
#define TILE_BYTES   16384
#define SPLIT_BYTES  32768

// ---------------- device scratch ----------------
__device__ float               g_f[(size_t)NB*NPTS*COUT];
__device__ __align__(1024) unsigned char g_fsplit[(size_t)NB*NTILES*3*SPLIT_BYTES];  // 25.2 MB
__device__ __align__(1024) unsigned char g_w2split[(size_t)MTILES*3*SPLIT_BYTES];    // 3 MB
__device__ unsigned long long  g_best[NB*MPTS];
__device__ int                 g_idx[NB*MPTS];

// ---------------- helpers ----------------
__device__ __forceinline__ uint32_t smem_u32(const void* p) {
    uint32_t a;
    asm("{ .reg .u64 t; cvta.to.shared.u64 t, %1; cvt.u32.u64 %0, t; }" : "=r"(a) : "l"(p));
    return a;
}
#define SW128(x) ((x) ^ (((x) >> 3) & 0x70))

__device__ __forceinline__ uint32_t enc_f(float x) {
    uint32_t u = __float_as_uint(x);
    return u ^ (((uint32_t)((int32_t)u >> 31)) | 0x80000000u);
}
struct Split3 { __nv_bfloat16 a, b, c; };
__device__ __forceinline__ Split3 split3(float v) {
    Split3 s;
    s.a = __float2bfloat16_rn(v);
    float r = v - __bfloat162float(s.a);
    s.b = __float2bfloat16_rn(r);
    float r2 = r - __bfloat162float(s.b);
    s.c = __float2bfloat16_rn(r2);
    return s;
}
__device__ __forceinline__ uint32_t pk2(__nv_bfloat16 lo, __nv_bfloat16 hi) {
    __nv_bfloat162 t(lo, hi);
    return *(uint32_t*)&t;
}

__device__ __forceinline__ void ldsm_x4(uint32_t* r, uint32_t addr) {
    asm volatile("ldmatrix.sync.aligned.m8n8.x4.shared.b16 {%0,%1,%2,%3}, [%4];"
        : "=r"(r[0]), "=r"(r[1]), "=r"(r[2]), "=r"(r[3]) : "r"(addr));
}
// B operand: smem tile is n-major (k contiguous) -> NON-trans ldmatrix gives
// exactly the mma.row.col B fragment (k=(lane%4)*2+e, n=lane/4). (.trans here
// was the Round-7 bug: it delivered the k/n-swapped fragment.)
__device__ __forceinline__ void ldsm_x2(uint32_t* r, uint32_t addr) {
    asm volatile("ldmatrix.sync.aligned.m8n8.x2.shared.b16 {%0,%1}, [%2];"
        : "=r"(r[0]), "=r"(r[1]) : "r"(addr));
}
__device__ __forceinline__ void mma16816(float* c, const uint32_t* a, const uint32_t* b) {
    asm volatile("mma.sync.aligned.m16n8k16.row.col.f32.bf16.bf16.f32 "
        "{%0,%1,%2,%3}, {%4,%5,%6,%7}, {%8,%9}, {%0,%1,%2,%3};"
        : "+f"(c[0]), "+f"(c[1]), "+f"(c[2]), "+f"(c[3])
        : "r"(a[0]), "r"(a[1]), "r"(a[2]), "r"(a[3]), "r"(b[0]), "r"(b[1]));
}
__device__ __forceinline__ void cp16(uint32_t dst, const void* src) {
    asm volatile("cp.async.cg.shared.global [%0], [%1], 16;" :: "r"(dst), "l"(src) : "memory");
}
#define CP_COMMIT() asm volatile("cp.async.commit_group;" ::: "memory")
#define CP_WAIT0()  asm volatile("cp.async.wait_group 0;" ::: "memory")

// ---------------- kernel 0: init ----------------
__global__ void k_init() {
    int i = blockIdx.x * blockDim.x + threadIdx.x;
    if (i < NB * MPTS) g_best[i] = 0ULL;
}

// ---------------- kernel W: split W2^T into bf16 SW128 tiles ----------------
// tile layout per mt: [split][khalf][128 m-rows x 64 k x bf16, SW128]
__global__ void k_w2split(const float* __restrict__ W2) {
    int mt = blockIdx.x, ml = threadIdx.x;
    for (int k = 0; k < COUT; k++) {
        float v = W2[(size_t)k * MPTS + mt * 128 + ml];
        Split3 s = split3(v);
        size_t base = (size_t)mt * 3 * SPLIT_BYTES + (k >> 6) * TILE_BYTES;
        uint32_t off = SW128((uint32_t)(ml * 128 + (k & 63) * 2));
        *(__nv_bfloat16*)(g_w2split + base + off) = s.a;
        *(__nv_bfloat16*)(g_w2split + base + SPLIT_BYTES + off) = s.b;
        *(__nv_bfloat16*)(g_w2split + base + 2 * SPLIT_BYTES + off) = s.c;
    }
}

// ---------------- kernel A: f = relu(feats^T W1 + b1), fp32 + bf16 splits ----
__global__ __launch_bounds__(256) void k_feat(const float* __restrict__ feats,
                                              const float* __restrict__ W1,
                                              const float* __restrict__ b1) {
    extern __shared__ float sm[];
    float* sX = sm;              // [64][132]
    float* sW = sm + 64 * 132;   // [64][128]
    const int b  = blockIdx.y;
    const int ntile = blockIdx.x;
    const int n0 = ntile * 128;
    const int t  = threadIdx.x;

#pragma unroll
    for (int i = 0; i < 8; i++) {
        int lin = t + 256 * i;
        int c = lin >> 5, q = lin & 31;
        float4 v = *(const float4*)(feats + ((size_t)(b * CIN + c)) * NPTS + n0 + 4 * q);
        *(float4*)(sX + c * 132 + 4 * q) = v;
    }
#pragma unroll
    for (int i = 0; i < 8; i++) {
        int lin = t + 256 * i;
        int c = lin >> 5, q = lin & 31;
        *(float4*)(sW + c * 128 + 4 * q) = *(const float4*)(W1 + c * 128 + 4 * q);
    }
    __syncthreads();

    const int db = (t & 15) * 8;
    const int nb = (t >> 4) * 8;

    float acc[8][8];
#pragma unroll
    for (int i = 0; i < 8; i++)
#pragma unroll
        for (int j = 0; j < 8; j++) acc[i][j] = 0.0f;

    for (int c = 0; c < CIN; c++) {
        float x[8], w[8];
#pragma unroll
        for (int i = 0; i < 8; i++) x[i] = sX[c * 132 + nb + i];
#pragma unroll
        for (int j = 0; j < 8; j++) w[j] = sW[c * 128 + db + j];
#pragma unroll
        for (int i = 0; i < 8; i++)
#pragma unroll
            for (int j = 0; j < 8; j++) acc[i][j] = fmaf(x[i], w[j], acc[i][j]);
    }

    float bias[8];
#pragma unroll
    for (int j = 0; j < 8; j++) bias[j] = b1[db + j];

    const int h = db >> 6;
    unsigned char* tile0 = g_fsplit + (((size_t)(b * NTILES + ntile) * 3 + 0) * 2 + h) * TILE_BYTES;

#pragma unroll
    for (int i = 0; i < 8; i++) {
        float o[8];
#pragma unroll
        for (int j = 0; j < 8; j++) o[j] = fmaxf(acc[i][j] + bias[j], 0.0f);
        float* dst = g_f + ((size_t)(b) * NPTS + n0 + nb + i) * COUT + db;
        *(float4*)(dst)     = make_float4(o[0], o[1], o[2], o[3]);
        *(float4*)(dst + 4) = make_float4(o[4], o[5], o[6], o[7]);

        uint4 p0, p1, p2;
        Split3 s0 = split3(o[0]), s1 = split3(o[1]), s2 = split3(o[2]), s3 = split3(o[3]);
        Split3 s4 = split3(o[4]), s5 = split3(o[5]), s6 = split3(o[6]), s7 = split3(o[7]);
        p0.x = pk2(s0.a, s1.a); p0.y = pk2(s2.a, s3.a); p0.z = pk2(s4.a, s5.a); p0.w = pk2(s6.a, s7.a);
        p1.x = pk2(s0.b, s1.b); p1.y = pk2(s2.b, s3.b); p1.z = pk2(s4.b, s5.b); p1.w = pk2(s6.b, s7.b);
        p2.x = pk2(s0.c, s1.c); p2.y = pk2(s2.c, s3.c); p2.z = pk2(s4.c, s5.c); p2.w = pk2(s6.c, s7.c);
        uint32_t off = SW128((uint32_t)((nb + i) * 128 + (db & 63) * 2));
        *(uint4*)(tile0 + off) = p0;
        *(uint4*)(tile0 + 2 * TILE_BYTES + off) = p1;
        *(uint4*)(tile0 + 4 * TILE_BYTES + off) = p2;
    }
}

// ---------------- kernel B: HMMA w-GEMM (6-product bf16 split) + gumbel + argmax
// grid (32 mt, 4 np, 2 b), 256 threads = 8 warps; warp tile 64m x 32n.
#define SM_W2   0                       // 3 x 32768 = 98304
#define SM_F    98304                   // 2 x 32768 = 65536
#define SM_BEST 163840                  // 128 x 8    = 1024
#define SM_TOT  164864

__global__ __launch_bounds__(256, 1) void k_main(const float* __restrict__ u) {
    extern __shared__ unsigned char smc[];
    const uint32_t smem_base = smem_u32(smc);
    const int t = threadIdx.x, lane = t & 31, wid = t >> 5;
    const int wm = wid >> 2;           // m half (64)
    const int wn = wid & 3;            // n quarter (32)
    const int mt = blockIdx.x, np = blockIdx.y, b = blockIdx.z;
    unsigned long long* sBest = (unsigned long long*)(smc + SM_BEST);

    if (t < 128) sBest[t] = 0ULL;

    // W2 splits resident (linear copy of SW128 images)
    {
        const uint4* src = (const uint4*)(g_w2split + (size_t)mt * 3 * SPLIT_BYTES);
        uint4* dst = (uint4*)(smc + SM_W2);
        for (int i = t; i < 3 * SPLIT_BYTES / 16; i += 256) dst[i] = src[i];
    }
    __syncthreads();

    const unsigned char* fbase = g_fsplit + (size_t)(b * NTILES + np * NCHUNKS) * 3 * SPLIT_BYTES;

    // prefetch stage 0
    {
        uint32_t d = smem_base + SM_F + (t * 16);
        const unsigned char* s = fbase + t * 16;
#pragma unroll
        for (int i = 0; i < 8; i++) cp16(d + i * 4096, s + i * 4096);
        CP_COMMIT();
    }

    // ldmatrix address components (within a 16KB half image)
    const uint32_t a_row = (uint32_t)(wm * 64 + (lane & 15)) * 128 + (lane >> 4) * 16;
    const int lb = lane & 15;
    const uint32_t b_row = (uint32_t)(wn * 32 + (lb & 7)) * 128 + ((lb >> 3) & 1) * 16;

    float acc[4][4][4];
#pragma unroll
    for (int mi = 0; mi < 4; mi++)
#pragma unroll
        for (int ni = 0; ni < 4; ni++)
#pragma unroll
            for (int q = 0; q < 4; q++) acc[mi][ni][q] = 0.0f;

    unsigned long long bestk[8];
#pragma unroll
    for (int q = 0; q < 8; q++) bestk[q] = 0ULL;

    const float* ubase = u + (size_t)b * NPTS * MPTS + (size_t)mt * 128
                           + wm * 64 + (lane >> 2);

    for (int st = 0; st < NSTAGES; st++) {
        const int c = st / 3, s = st - 3 * c;
        const int buf = st & 1;

        CP_WAIT0();
        __syncthreads();
        // prefetch next stage into other buffer
        if (st + 1 < NSTAGES) {
            uint32_t d = smem_base + SM_F + (buf ^ 1) * SPLIT_BYTES + t * 16;
            const unsigned char* sp = fbase + (size_t)(st + 1) * SPLIT_BYTES + t * 16;
#pragma unroll
            for (int i = 0; i < 8; i++) cp16(d + i * 4096, sp + i * 4096);
        }
        CP_COMMIT();

        const int nprod = (s == 0) ? 3 : (s == 1 ? 2 : 1);
        const uint32_t fb0 = smem_base + SM_F + buf * SPLIT_BYTES;

#pragma unroll
        for (int kh = 0; kh < 2; kh++) {
            const uint32_t fhb = fb0 + kh * TILE_BYTES;
            const uint32_t whb = smem_base + SM_W2 + kh * TILE_BYTES;
#pragma unroll
            for (int ks = 0; ks < 4; ks++) {
                uint32_t bf[4][2];
#pragma unroll
                for (int ni = 0; ni < 4; ni++)
                    ldsm_x2(bf[ni], fhb + SW128(b_row + (uint32_t)ni * 8 * 128 + ks * 32));
                for (int sw = 0; sw < nprod; sw++) {
                    const uint32_t wsb = whb + sw * SPLIT_BYTES;
#pragma unroll
                    for (int mi = 0; mi < 4; mi++) {
                        uint32_t af[4];
                        ldsm_x4(af, wsb + SW128(a_row + (uint32_t)mi * 16 * 128 + ks * 32));
#pragma unroll
                        for (int ni = 0; ni < 4; ni++)
                            mma16816(acc[mi][ni], af, bf[ni]);
                    }
                }
            }
        }

        if (s == 2) {
            // epilogue for chunk c: gumbel + argmax, then reset acc
            const int n0c = np * NPART + c * 128;
#pragma unroll
            for (int mi = 0; mi < 4; mi++)
#pragma unroll
                for (int hh = 0; hh < 2; hh++) {
                    const int slot = mi * 2 + hh;
                    uint32_t bk = (uint32_t)(bestk[slot] >> 32);
                    int bn = (int)(0xFFFFFFFFu - (uint32_t)bestk[slot]);
#pragma unroll
                    for (int ni = 0; ni < 4; ni++)
#pragma unroll
                        for (int j = 0; j < 2; j++) {
                            const int n_l = wn * 32 + ni * 8 + 2 * (lane & 3) + j;
                            float val = acc[mi][ni][hh * 2 + j];
                            float uu = __ldg(ubase + (size_t)(n0c + n_l) * MPTS + mi * 16 + hh * 8);
                            float t1 = -logf(uu + EPSF);
                            float g  = -logf(t1 + EPSF);
                            uint32_t ek = enc_f(val + g);
                            if (ek > bk) { bk = ek; bn = n0c + n_l; }
                            acc[mi][ni][hh * 2 + j] = 0.0f;
                        }
                    bestk[slot] = ((unsigned long long)bk << 32) | (0xFFFFFFFFu - (uint32_t)bn);
                }
        }
    }

    // reduce
#pragma unroll
    for (int mi = 0; mi < 4; mi++)
#pragma unroll
        for (int hh = 0; hh < 2; hh++) {
            int m_local = wm * 64 + mi * 16 + hh * 8 + (lane >> 2);
            atomicMax(&sBest[m_local], bestk[mi * 2 + hh]);
        }
    __syncthreads();
    if (t < 128) atomicMax(&g_best[(size_t)b * MPTS + mt * 128 + t], sBest[t]);
}

// ---------------- kernel C: decode idx, write xyz + indices ----------------
__global__ void k_pick(const float* __restrict__ xyzs, float* __restrict__ out) {
    int i = blockIdx.x * blockDim.x + threadIdx.x;
    if (i >= NB * MPTS) return;
    int b = i / MPTS;
    unsigned long long key = g_best[i];
    int n = (int)(0xFFFFFFFFu - (unsigned int)(key & 0xFFFFFFFFull));
    g_idx[i] = n;
    const float* x = xyzs + ((size_t)b * NPTS + n) * 3;
    out[XYZ_OFF + 3 * i + 0] = x[0];
    out[XYZ_OFF + 3 * i + 1] = x[1];
    out[XYZ_OFF + 3 * i + 2] = x[2];
    out[IDX_OFF + i] = (float)n;
}

// ---------------- kernel D: gather features (b, Cout, M) ----------------
__global__ void k_gather(float* __restrict__ out) {
    int j = blockIdx.x * blockDim.x + threadIdx.x;
    if (j >= NB * COUT * MPTS) return;
    int b = j / (COUT * MPTS);
    int d = (j / MPTS) % COUT;
    int m = j % MPTS;
    int n = g_idx[b * MPTS + m];
    out[FEAT_OFF + j] = g_f[((size_t)b * NPTS + n) * COUT + d];
}

// ---------------- launch ----------------
extern "C" void kernel_launch(void* const* d_in, const int* in_sizes, int n_in,
                              void* d_out, int out_size) {
    const float* xyzs  = (const float*)d_in[0];
    const float* feats = (const float*)d_in[1];
    const float* u     = (const float*)d_in[2];
    const float* W1    = (const float*)d_in[3];
    const float* b1    = (const float*)d_in[4];
    const float* W2    = (const float*)d_in[5];
    // d_in[6] = b2: constant per m-column -> cannot change the argmax; unused.
    float* out = (float*)d_out;

    const int smemA = (64 * 132 + 64 * 128) * 4;
    cudaFuncSetAttribute(k_feat, cudaFuncAttributeMaxDynamicSharedMemorySize, smemA);
    cudaFuncSetAttribute(k_main, cudaFuncAttributeMaxDynamicSharedMemorySize, SM_TOT);

    k_init<<<(NB * MPTS + 255) / 256, 256>>>();
    k_w2split<<<MTILES, 128>>>(W2);
    k_feat<<<dim3(NTILES, NB), 256, smemA>>>(feats, W1, b1);
    k_main<<<dim3(MTILES, NSPLIT, NB), 256, SM_TOT>>>(u);
    k_pick<<<(NB * MPTS + 255) / 256, 256>>>(xyzs, out);
    k_gather<<<(NB * COUT * MPTS + 255) / 256, 256>>>(out);
}

// round 11
// speedup vs baseline: 1.5160x; 1.5160x over previous
#include <cuda_runtime.h>
#include <cuda_fp16.h>
#include <cstdint>
#include <math.h>

#define NB    2
#define NPTS  16384
#define MPTS  4096
#define CIN   64
#define COUT  128
#define EPSF  1e-10f

#define NSPLIT   16
#define NPART    (NPTS/NSPLIT)      // 1024
#define NCHUNKS  (NPART/128)        // 8
#define NTILES   (NPTS/128)         // 128 per batch
#define MTILES   (MPTS/128)         // 32
#define NSTAGES  (NCHUNKS*2)        // 16 (2 fp16 splits per chunk)
#define NUNITS   (MTILES*NSPLIT*NB) // 1024
#define NCTA     152

#define XYZ_OFF  0
#define FEAT_OFF (NB*MPTS*3)
#define IDX_OFF  (FEAT_OFF + NB*COUT*MPTS)

// tile block: [128 rows][64 fp16 cols] SW128 image = 16384 B; split (K=128) = 2 blocks
#define TILE_BYTES   16384
#define SPLIT_BYTES  32768

// ---------------- device scratch ----------------
__device__ __align__(1024) unsigned char g_fsplit[(size_t)NB*NTILES*2*SPLIT_BYTES];  // 16.8 MB
__device__ __align__(1024) unsigned char g_w2split[(size_t)MTILES*2*SPLIT_BYTES];    // 2 MB
__device__ unsigned long long  g_best[NB*MPTS];
__device__ int                 g_idx[NB*MPTS];
__device__ int                 g_ctr;

// ---------------- helpers ----------------
__device__ __forceinline__ uint32_t smem_u32(const void* p) {
    uint32_t a;
    asm("{ .reg .u64 t; cvta.to.shared.u64 t, %1; cvt.u32.u64 %0, t; }" : "=r"(a) : "l"(p));
    return a;
}
#define SW128(x) ((x) ^ (((x) >> 3) & 0x70))

__device__ __forceinline__ uint32_t enc_f(float x) {
    uint32_t u = __float_as_uint(x);
    return u ^ (((uint32_t)((int32_t)u >> 31)) | 0x80000000u);
}
__device__ __forceinline__ uint32_t pk2h(__half lo, __half hi) {
    __half2 t(lo, hi);
    return *(uint32_t*)&t;
}
// fast accurate -ln(x) for normal fp32 x: atanh-form poly, abs err ~1e-7.
__device__ __forceinline__ float fast_nlog(float x) {
    int i = __float_as_int(x);
    int tt = i - 0x3F3504F3;                   // bits of sqrt(0.5)
    int e  = tt >> 23;
    float m = __int_as_float(i - (e << 23));   // m in [0.7071, 1.4142)
    float s = __fdividef(m - 1.0f, m + 1.0f);  // |s| <= 0.1716
    float s2 = s * s;
    float p = fmaf(s2, 0.11111111f, 0.14285715f);
    p = fmaf(s2, p, 0.2f);
    p = fmaf(s2, p, 0.33333334f);
    p = fmaf(s2, p, 1.0f);
    float lm = (s + s) * p;                    // ln(m)
    float ef = (float)e;
    float res = fmaf(ef, -0.693359375f, -lm);  // -e*ln2_hi - ln(m)
    return fmaf(ef, 2.12194440e-4f, res);      // + e*ln2_lo_neg
}

__device__ __forceinline__ void ldsm_x4(uint32_t* r, uint32_t addr) {
    asm volatile("ldmatrix.sync.aligned.m8n8.x4.shared.b16 {%0,%1,%2,%3}, [%4];"
        : "=r"(r[0]), "=r"(r[1]), "=r"(r[2]), "=r"(r[3]) : "r"(addr));
}
__device__ __forceinline__ void mma16816(float* c, const uint32_t* a, const uint32_t* b) {
    asm volatile("mma.sync.aligned.m16n8k16.row.col.f32.f16.f16.f32 "
        "{%0,%1,%2,%3}, {%4,%5,%6,%7}, {%8,%9}, {%0,%1,%2,%3};"
        : "+f"(c[0]), "+f"(c[1]), "+f"(c[2]), "+f"(c[3])
        : "r"(a[0]), "r"(a[1]), "r"(a[2]), "r"(a[3]), "r"(b[0]), "r"(b[1]));
}
__device__ __forceinline__ void cp16(uint32_t dst, const void* src) {
    asm volatile("cp.async.cg.shared.global [%0], [%1], 16;" :: "r"(dst), "l"(src) : "memory");
}
#define CP_COMMIT() asm volatile("cp.async.commit_group;" ::: "memory")
#define CP_WAIT1()  asm volatile("cp.async.wait_group 1;" ::: "memory")

// ---------------- kernel W: split 64*W2^T into fp16 SW128 tiles + init ----------------
__global__ void k_w2split(const float* __restrict__ W2) {
    int mt = blockIdx.x, ml = threadIdx.x;
    if (mt == 0 && ml == 0) g_ctr = 0;
    for (int i = mt * 128 + ml; i < NB * MPTS; i += MTILES * 128) g_best[i] = 0ULL;
    unsigned char* base = g_w2split + (size_t)mt * 2 * SPLIT_BYTES;
    for (int k = 0; k < COUT; k++) {
        float v = W2[(size_t)k * MPTS + mt * 128 + ml] * 64.0f;
        __half a = __float2half_rn(v);
        __half b = __float2half_rn(v - __half2float(a));
        uint32_t off = (uint32_t)(k >> 6) * TILE_BYTES + SW128((uint32_t)(ml * 128 + (k & 63) * 2));
        *(__half*)(base + off) = a;
        *(__half*)(base + SPLIT_BYTES + off) = b;
    }
}

// ---------------- kernel A: f = relu(feats^T W1 + b1) -> fp16 2-split tiles ----
__global__ __launch_bounds__(256) void k_feat(const float* __restrict__ feats,
                                              const float* __restrict__ W1,
                                              const float* __restrict__ b1) {
    extern __shared__ float sm[];
    float* sX = sm;              // [64][132]
    float* sW = sm + 64 * 132;   // [64][128]
    const int b  = blockIdx.y;
    const int ntile = blockIdx.x;
    const int n0 = ntile * 128;
    const int t  = threadIdx.x;

#pragma unroll
    for (int i = 0; i < 8; i++) {
        int lin = t + 256 * i;
        int c = lin >> 5, q = lin & 31;
        float4 v = *(const float4*)(feats + ((size_t)(b * CIN + c)) * NPTS + n0 + 4 * q);
        *(float4*)(sX + c * 132 + 4 * q) = v;
    }
#pragma unroll
    for (int i = 0; i < 8; i++) {
        int lin = t + 256 * i;
        int c = lin >> 5, q = lin & 31;
        *(float4*)(sW + c * 128 + 4 * q) = *(const float4*)(W1 + c * 128 + 4 * q);
    }
    __syncthreads();

    const int db = (t & 15) * 8;
    const int nb = (t >> 4) * 8;

    float acc[8][8];
#pragma unroll
    for (int i = 0; i < 8; i++)
#pragma unroll
        for (int j = 0; j < 8; j++) acc[i][j] = 0.0f;

    for (int c = 0; c < CIN; c++) {
        float x[8], w[8];
#pragma unroll
        for (int i = 0; i < 8; i++) x[i] = sX[c * 132 + nb + i];
#pragma unroll
        for (int j = 0; j < 8; j++) w[j] = sW[c * 128 + db + j];
#pragma unroll
        for (int i = 0; i < 8; i++)
#pragma unroll
            for (int j = 0; j < 8; j++) acc[i][j] = fmaf(x[i], w[j], acc[i][j]);
    }

    float bias[8];
#pragma unroll
    for (int j = 0; j < 8; j++) bias[j] = b1[db + j];

    unsigned char* tb = g_fsplit + ((size_t)(b * NTILES + ntile) * 2) * SPLIT_BYTES
                      + (db >> 6) * TILE_BYTES;

#pragma unroll
    for (int i = 0; i < 8; i++) {
        float o[8];
#pragma unroll
        for (int j = 0; j < 8; j++) o[j] = fmaxf(acc[i][j] + bias[j], 0.0f);
        __half ha[8], hb[8];
#pragma unroll
        for (int j = 0; j < 8; j++) {
            ha[j] = __float2half_rn(o[j]);
            hb[j] = __float2half_rn(o[j] - __half2float(ha[j]));
        }
        uint4 pa, pb;
        pa.x = pk2h(ha[0], ha[1]); pa.y = pk2h(ha[2], ha[3]);
        pa.z = pk2h(ha[4], ha[5]); pa.w = pk2h(ha[6], ha[7]);
        pb.x = pk2h(hb[0], hb[1]); pb.y = pk2h(hb[2], hb[3]);
        pb.z = pk2h(hb[4], hb[5]); pb.w = pk2h(hb[6], hb[7]);
        uint32_t off = SW128((uint32_t)((nb + i) * 128 + (db & 63) * 2));
        *(uint4*)(tb + off) = pa;
        *(uint4*)(tb + SPLIT_BYTES + off) = pb;
    }
}

// ---------------- kernel B: persistent HMMA w-GEMM (fp16 2-split, 3 products) ----
#define SM_W2   0                       // 2 x 32768 = 65536
#define SM_F    65536                   // 3 x 32768 = 98304
#define SM_BEST 163840                  // 128 x 8    = 1024
#define SM_TOT  164864

__global__ __launch_bounds__(512, 1) void k_main(const float* __restrict__ u) {
    extern __shared__ unsigned char smc[];
    __shared__ int s_uid;
    const uint32_t smem_base = smem_u32(smc);
    const int t = threadIdx.x, lane = t & 31, wid = t >> 5;
    const int wm = wid >> 2, wn = wid & 3;
    unsigned long long* sBest = (unsigned long long*)(smc + SM_BEST);

    // A (W2, m-major): x4 -> {m0-7/k0-7, m8-15/k0-7, m0-7/k8-15, m8-15/k8-15} = a0..a3
    const uint32_t a_row = (uint32_t)((wm * 32 + (lane & 15)) * 128 + (lane >> 4) * 16);
    // B (f, n-major): x4 -> {n0-7/k0-7, n0-7/k8-15, n8-15/k0-7, n8-15/k8-15}
    const uint32_t b_row = (uint32_t)((wn * 32 + ((lane & 16) >> 1) + (lane & 7)) * 128
                                      + ((lane >> 3) & 1) * 16);

    while (true) {
        if (t == 0) s_uid = atomicAdd(&g_ctr, 1);
        __syncthreads();
        const int uid = s_uid;
        if (uid >= NUNITS) break;
        const int mt = uid & 31, b = (uid >> 5) & 1, np = uid >> 6;

        if (t < 128) sBest[t] = 0ULL;
        {   // W2 splits (64KB) -> smem
            const uint4* src = (const uint4*)(g_w2split + (size_t)mt * 2 * SPLIT_BYTES);
            uint4* dst = (uint4*)(smc + SM_W2);
#pragma unroll
            for (int i = 0; i < 8; i++) dst[t + 512 * i] = src[t + 512 * i];
        }
        __syncthreads();

        const unsigned char* fsrc = g_fsplit + ((size_t)(b * NTILES + np * NCHUNKS) * 2) * SPLIT_BYTES;
        // prologue: stages 0,1
#pragma unroll
        for (int pg = 0; pg < 2; pg++) {
            uint32_t d = smem_base + SM_F + pg * SPLIT_BYTES + t * 16;
            const unsigned char* sp = fsrc + (size_t)pg * SPLIT_BYTES + t * 16;
#pragma unroll
            for (int i = 0; i < 4; i++) cp16(d + i * 8192, sp + i * 8192);
            CP_COMMIT();
        }

        float acc[2][4][4];
#pragma unroll
        for (int mi = 0; mi < 2; mi++)
#pragma unroll
            for (int ni = 0; ni < 4; ni++)
#pragma unroll
                for (int q = 0; q < 4; q++) acc[mi][ni][q] = 0.0f;
        float bv[4]; int bn[4];
#pragma unroll
        for (int q = 0; q < 4; q++) { bv[q] = -1e38f; bn[q] = 0; }

        const float* u_unit = u + (size_t)b * NPTS * MPTS
                            + ((size_t)np * NPART + wn * 32 + 2 * (lane & 3)) * MPTS
                            + (mt * 128 + wm * 32 + (lane >> 2));
        const int n_unit = np * NPART + wn * 32 + 2 * (lane & 3);

        int buf = 0;
        for (int st = 0; st < NSTAGES; st++) {
            const int cc = st >> 1, ss = st & 1;
            CP_WAIT1();
            __syncthreads();
            if (st + 2 < NSTAGES) {
                int nb3 = buf + 2; if (nb3 >= 3) nb3 -= 3;
                uint32_t d = smem_base + SM_F + nb3 * SPLIT_BYTES + t * 16;
                const unsigned char* sp = fsrc + (size_t)(st + 2) * SPLIT_BYTES + t * 16;
#pragma unroll
                for (int i = 0; i < 4; i++) cp16(d + i * 8192, sp + i * 8192);
            }
            CP_COMMIT();
            const uint32_t fb0 = smem_base + SM_F + buf * SPLIT_BYTES;

            if (ss == 0) {
                // f_a x {w_a, w_b}
#pragma unroll
                for (int kh = 0; kh < 2; kh++) {
                    const uint32_t fhb = fb0 + kh * TILE_BYTES;
                    const uint32_t whb = smem_base + SM_W2 + kh * TILE_BYTES;
#pragma unroll
                    for (int ks = 0; ks < 4; ks++) {
                        uint32_t bf0[4], bf1[4];
                        ldsm_x4(bf0, fhb + SW128(b_row + ks * 32));
                        ldsm_x4(bf1, fhb + SW128(b_row + 2048 + ks * 32));
#pragma unroll
                        for (int sw = 0; sw < 2; sw++)
#pragma unroll
                            for (int mi = 0; mi < 2; mi++) {
                                uint32_t af[4];
                                ldsm_x4(af, whb + sw * SPLIT_BYTES + SW128(a_row + mi * 2048 + ks * 32));
                                mma16816(acc[mi][0], af, bf0);
                                mma16816(acc[mi][1], af, bf0 + 2);
                                mma16816(acc[mi][2], af, bf1);
                                mma16816(acc[mi][3], af, bf1 + 2);
                            }
                    }
                }
            } else {
                // f_b x w_a, epilogue interleaved per mi
                const float* uc = u_unit + (size_t)(cc * 128) * MPTS;
                const int n0 = n_unit + cc * 128;
#pragma unroll
                for (int mi = 0; mi < 2; mi++) {
#pragma unroll
                    for (int kh = 0; kh < 2; kh++) {
                        const uint32_t fhb = fb0 + kh * TILE_BYTES;
                        const uint32_t whb = smem_base + SM_W2 + kh * TILE_BYTES;
#pragma unroll
                        for (int ks = 0; ks < 4; ks++) {
                            uint32_t bf0[4], bf1[4], af[4];
                            ldsm_x4(bf0, fhb + SW128(b_row + ks * 32));
                            ldsm_x4(bf1, fhb + SW128(b_row + 2048 + ks * 32));
                            ldsm_x4(af, whb + SW128(a_row + mi * 2048 + ks * 32));
                            mma16816(acc[mi][0], af, bf0);
                            mma16816(acc[mi][1], af, bf0 + 2);
                            mma16816(acc[mi][2], af, bf1);
                            mma16816(acc[mi][3], af, bf1 + 2);
                        }
                    }
#pragma unroll
                    for (int hh = 0; hh < 2; hh++) {
                        const int slot = mi * 2 + hh;
                        float lbv = bv[slot]; int lbn = bn[slot];
#pragma unroll
                        for (int ni = 0; ni < 4; ni++)
#pragma unroll
                            for (int j = 0; j < 2; j++) {
                                float val = acc[mi][ni][hh * 2 + j];
                                float uu = __ldg(uc + (size_t)(ni * 8 + j) * MPTS + mi * 16 + hh * 8);
                                float t1 = fast_nlog(uu + EPSF);
                                float g  = fast_nlog(t1 + EPSF);
                                float sc = fmaf(val, 0.015625f, g);   // /64 W2 scale
                                if (sc > lbv) { lbv = sc; lbn = n0 + ni * 8 + j; }
                                acc[mi][ni][hh * 2 + j] = 0.0f;
                            }
                        bv[slot] = lbv; bn[slot] = lbn;
                    }
                }
            }
            buf++; if (buf == 3) buf = 0;
        }

        // flush unit results (keys: order-preserving float encode, ~n for tie->lowest n)
#pragma unroll
        for (int mi = 0; mi < 2; mi++)
#pragma unroll
            for (int hh = 0; hh < 2; hh++) {
                const int slot = mi * 2 + hh;
                unsigned long long key = ((unsigned long long)enc_f(bv[slot]) << 32)
                                       | (0xFFFFFFFFu - (uint32_t)bn[slot]);
                atomicMax(&sBest[wm * 32 + mi * 16 + hh * 8 + (lane >> 2)], key);
            }
        __syncthreads();
        if (t < 128) atomicMax(&g_best[(size_t)b * MPTS + mt * 128 + t], sBest[t]);
        __syncthreads();
    }
}

// ---------------- kernel C: decode idx, write xyz + indices ----------------
__global__ void k_pick(const float* __restrict__ xyzs, float* __restrict__ out) {
    int i = blockIdx.x * blockDim.x + threadIdx.x;
    if (i >= NB * MPTS) return;
    int b = i / MPTS;
    unsigned long long key = g_best[i];
    int n = (int)(0xFFFFFFFFu - (unsigned int)(key & 0xFFFFFFFFull));
    g_idx[i] = n;
    const float* x = xyzs + ((size_t)b * NPTS + n) * 3;
    out[XYZ_OFF + 3 * i + 0] = x[0];
    out[XYZ_OFF + 3 * i + 1] = x[1];
    out[XYZ_OFF + 3 * i + 2] = x[2];
    out[IDX_OFF + i] = (float)n;
}

// ---------------- kernel D: gather features (b, Cout, M) from fp16 splits ----
__global__ void k_gather(float* __restrict__ out) {
    int j = blockIdx.x * blockDim.x + threadIdx.x;
    if (j >= NB * COUT * MPTS) return;
    int b = j / (COUT * MPTS);
    int d = (j / MPTS) % COUT;
    int m = j % MPTS;
    int n = g_idx[b * MPTS + m];
    const unsigned char* tb = g_fsplit + ((size_t)(b * NTILES + (n >> 7)) * 2) * SPLIT_BYTES
                            + (d >> 6) * TILE_BYTES;
    uint32_t off = SW128((uint32_t)((n & 127) * 128 + (d & 63) * 2));
    float fa = __half2float(*(const __half*)(tb + off));
    float fb = __half2float(*(const __half*)(tb + SPLIT_BYTES + off));
    out[FEAT_OFF + j] = fa + fb;
}

// ---------------- launch ----------------
extern "C" void kernel_launch(void* const* d_in, const int* in_sizes, int n_in,
                              void* d_out, int out_size) {
    const float* xyzs  = (const float*)d_in[0];
    const float* feats = (const float*)d_in[1];
    const float* u     = (const float*)d_in[2];
    const float* W1    = (const float*)d_in[3];
    const float* b1    = (const float*)d_in[4];
    const float* W2    = (const float*)d_in[5];
    // d_in[6] = b2: constant per m-column -> cannot change the argmax; unused.
    float* out = (float*)d_out;

    const int smemA = (64 * 132 + 64 * 128) * 4;
    cudaFuncSetAttribute(k_feat, cudaFuncAttributeMaxDynamicSharedMemorySize, smemA);
    cudaFuncSetAttribute(k_main, cudaFuncAttributeMaxDynamicSharedMemorySize, SM_TOT);

    k_w2split<<<MTILES, 128>>>(W2);
    k_feat<<<dim3(NTILES, NB), 256, smemA>>>(feats, W1, b1);
    k_main<<<NCTA, 512, SM_TOT>>>(u);
    k_pick<<<(NB * MPTS + 255) / 256, 256>>>(xyzs, out);
    k_gather<<<(NB * COUT * MPTS + 255) / 256, 256>>>(out);
}

// round 12
// speedup vs baseline: 1.6530x; 1.0904x over previous
#include <cuda_runtime.h>
#include <cuda_fp16.h>
#include <cstdint>
#include <math.h>

#define NB    2
#define NPTS  16384
#define MPTS  4096
#define CIN   64
#define COUT  128
#define EPSF  1e-10f

#define NSPLIT   16
#define NPART    (NPTS/NSPLIT)      // 1024
#define NCHUNKS  (NPART/128)        // 8
#define NTILES   (NPTS/128)         // 128 per batch
#define MTILES   (MPTS/128)         // 32
#define NUNITS   (MTILES*NSPLIT*NB) // 1024
#define NCTA     152

#define XYZ_OFF  0
#define FEAT_OFF (NB*MPTS*3)
#define IDX_OFF  (FEAT_OFF + NB*COUT*MPTS)

// tile block: [128 rows][64 fp16 cols] SW128 image = 16384 B
// per ntile: [f_a kh0, f_a kh1, f_b kh0, f_b kh1] = 65536 B contiguous
#define TILE_BYTES   16384
#define SPLIT_BYTES  32768
#define CHUNK_BYTES  65536

// ---------------- device scratch ----------------
__device__ __align__(1024) unsigned char g_fsplit[(size_t)NB*NTILES*2*SPLIT_BYTES];  // 16.8 MB
__device__ __align__(1024) unsigned char g_w2split[(size_t)MTILES*2*SPLIT_BYTES];    // 2 MB
__device__ unsigned long long  g_best[NB*MPTS];
__device__ int                 g_idx[NB*MPTS];
__device__ int                 g_ctr;

// ---------------- helpers ----------------
__device__ __forceinline__ uint32_t smem_u32(const void* p) {
    uint32_t a;
    asm("{ .reg .u64 t; cvta.to.shared.u64 t, %1; cvt.u32.u64 %0, t; }" : "=r"(a) : "l"(p));
    return a;
}
#define SW128(x) ((x) ^ (((x) >> 3) & 0x70))

__device__ __forceinline__ uint32_t enc_f(float x) {
    uint32_t u = __float_as_uint(x);
    return u ^ (((uint32_t)((int32_t)u >> 31)) | 0x80000000u);
}
__device__ __forceinline__ uint32_t pk2h(__half lo, __half hi) {
    __half2 t(lo, hi);
    return *(uint32_t*)&t;
}
// fast accurate -ln(x) for normal fp32 x: atanh-form poly, abs err ~1e-7.
__device__ __forceinline__ float fast_nlog(float x) {
    int i = __float_as_int(x);
    int tt = i - 0x3F3504F3;                   // bits of sqrt(0.5)
    int e  = tt >> 23;
    float m = __int_as_float(i - (e << 23));   // m in [0.7071, 1.4142)
    float s = __fdividef(m - 1.0f, m + 1.0f);  // |s| <= 0.1716
    float s2 = s * s;
    float p = fmaf(s2, 0.11111111f, 0.14285715f);
    p = fmaf(s2, p, 0.2f);
    p = fmaf(s2, p, 0.33333334f);
    p = fmaf(s2, p, 1.0f);
    float lm = (s + s) * p;                    // ln(m)
    float ef = (float)e;
    float res = fmaf(ef, -0.693359375f, -lm);  // -e*ln2_hi - ln(m)
    return fmaf(ef, 2.12194440e-4f, res);      // + e*ln2_lo_neg
}

__device__ __forceinline__ void ldsm_x4(uint32_t* r, uint32_t addr) {
    asm volatile("ldmatrix.sync.aligned.m8n8.x4.shared.b16 {%0,%1,%2,%3}, [%4];"
        : "=r"(r[0]), "=r"(r[1]), "=r"(r[2]), "=r"(r[3]) : "r"(addr));
}
__device__ __forceinline__ void mma16816(float* c, const uint32_t* a, const uint32_t* b) {
    asm volatile("mma.sync.aligned.m16n8k16.row.col.f32.f16.f16.f32 "
        "{%0,%1,%2,%3}, {%4,%5,%6,%7}, {%8,%9}, {%0,%1,%2,%3};"
        : "+f"(c[0]), "+f"(c[1]), "+f"(c[2]), "+f"(c[3])
        : "r"(a[0]), "r"(a[1]), "r"(a[2]), "r"(a[3]), "r"(b[0]), "r"(b[1]));
}
__device__ __forceinline__ void cp16(uint32_t dst, const void* src) {
    asm volatile("cp.async.cg.shared.global [%0], [%1], 16;" :: "r"(dst), "l"(src) : "memory");
}
#define CP_COMMIT() asm volatile("cp.async.commit_group;" ::: "memory")
#define CP_WAIT0()  asm volatile("cp.async.wait_group 0;" ::: "memory")

// ---------------- kernel W: split 64*W2^T into fp16 SW128 tiles + init ----------------
__global__ void k_w2split(const float* __restrict__ W2) {
    int mt = blockIdx.x, ml = threadIdx.x;
    if (mt == 0 && ml == 0) g_ctr = 0;
    for (int i = mt * 128 + ml; i < NB * MPTS; i += MTILES * 128) g_best[i] = 0ULL;
    unsigned char* base = g_w2split + (size_t)mt * 2 * SPLIT_BYTES;
    for (int k = 0; k < COUT; k++) {
        float v = W2[(size_t)k * MPTS + mt * 128 + ml] * 64.0f;
        __half a = __float2half_rn(v);
        __half b = __float2half_rn(v - __half2float(a));
        uint32_t off = (uint32_t)(k >> 6) * TILE_BYTES + SW128((uint32_t)(ml * 128 + (k & 63) * 2));
        *(__half*)(base + off) = a;
        *(__half*)(base + SPLIT_BYTES + off) = b;
    }
}

// ---------------- kernel A: f = relu(feats^T W1 + b1) -> fp16 2-split tiles ----
__global__ __launch_bounds__(256) void k_feat(const float* __restrict__ feats,
                                              const float* __restrict__ W1,
                                              const float* __restrict__ b1) {
    extern __shared__ float sm[];
    float* sX = sm;              // [64][132]
    float* sW = sm + 64 * 132;   // [64][128]
    const int b  = blockIdx.y;
    const int ntile = blockIdx.x;
    const int n0 = ntile * 128;
    const int t  = threadIdx.x;

#pragma unroll
    for (int i = 0; i < 8; i++) {
        int lin = t + 256 * i;
        int c = lin >> 5, q = lin & 31;
        float4 v = *(const float4*)(feats + ((size_t)(b * CIN + c)) * NPTS + n0 + 4 * q);
        *(float4*)(sX + c * 132 + 4 * q) = v;
    }
#pragma unroll
    for (int i = 0; i < 8; i++) {
        int lin = t + 256 * i;
        int c = lin >> 5, q = lin & 31;
        *(float4*)(sW + c * 128 + 4 * q) = *(const float4*)(W1 + c * 128 + 4 * q);
    }
    __syncthreads();

    const int db = (t & 15) * 8;
    const int nb = (t >> 4) * 8;

    float acc[8][8];
#pragma unroll
    for (int i = 0; i < 8; i++)
#pragma unroll
        for (int j = 0; j < 8; j++) acc[i][j] = 0.0f;

    for (int c = 0; c < CIN; c++) {
        float x[8], w[8];
#pragma unroll
        for (int i = 0; i < 8; i++) x[i] = sX[c * 132 + nb + i];
#pragma unroll
        for (int j = 0; j < 8; j++) w[j] = sW[c * 128 + db + j];
#pragma unroll
        for (int i = 0; i < 8; i++)
#pragma unroll
            for (int j = 0; j < 8; j++) acc[i][j] = fmaf(x[i], w[j], acc[i][j]);
    }

    float bias[8];
#pragma unroll
    for (int j = 0; j < 8; j++) bias[j] = b1[db + j];

    unsigned char* tb = g_fsplit + ((size_t)(b * NTILES + ntile) * 2) * SPLIT_BYTES
                      + (db >> 6) * TILE_BYTES;

#pragma unroll
    for (int i = 0; i < 8; i++) {
        float o[8];
#pragma unroll
        for (int j = 0; j < 8; j++) o[j] = fmaxf(acc[i][j] + bias[j], 0.0f);
        __half ha[8], hb[8];
#pragma unroll
        for (int j = 0; j < 8; j++) {
            ha[j] = __float2half_rn(o[j]);
            hb[j] = __float2half_rn(o[j] - __half2float(ha[j]));
        }
        uint4 pa, pb;
        pa.x = pk2h(ha[0], ha[1]); pa.y = pk2h(ha[2], ha[3]);
        pa.z = pk2h(ha[4], ha[5]); pa.w = pk2h(ha[6], ha[7]);
        pb.x = pk2h(hb[0], hb[1]); pb.y = pk2h(hb[2], hb[3]);
        pb.z = pk2h(hb[4], hb[5]); pb.w = pk2h(hb[6], hb[7]);
        uint32_t off = SW128((uint32_t)((nb + i) * 128 + (db & 63) * 2));
        *(uint4*)(tb + off) = pa;
        *(uint4*)(tb + SPLIT_BYTES + off) = pb;
    }
}

// ---------------- kernel B: persistent HMMA w-GEMM (fp16 2-split, 3 products) ----
// chunk-stage pipeline: one 64KB stage per chunk (f_a + f_b), double buffered.
#define SM_W2   0                       // 2 x 32768 = 65536
#define SM_F    65536                   // 2 x 65536 = 131072
#define SM_BEST 196608                  // 128 x 8
#define SM_TOT  197632

__global__ __launch_bounds__(512, 1) void k_main(const float* __restrict__ u) {
    extern __shared__ unsigned char smc[];
    __shared__ int s_uid;
    const uint32_t smem_base = smem_u32(smc);
    const int t = threadIdx.x, lane = t & 31, wid = t >> 5;
    const int wm = wid >> 2, wn = wid & 3;
    unsigned long long* sBest = (unsigned long long*)(smc + SM_BEST);

    // A (W2, m-major): x4 -> a0..a3 of mma.row.col
    const uint32_t a_row = (uint32_t)((wm * 32 + (lane & 15)) * 128 + (lane >> 4) * 16);
    // B (f, n-major): x4 -> {n0-7/k0-7, n0-7/k8-15, n8-15/k0-7, n8-15/k8-15}
    const uint32_t b_row = (uint32_t)((wn * 32 + ((lane & 16) >> 1) + (lane & 7)) * 128
                                      + ((lane >> 3) & 1) * 16);

    while (true) {
        if (t == 0) s_uid = atomicAdd(&g_ctr, 1);
        __syncthreads();
        const int uid = s_uid;
        if (uid >= NUNITS) break;
        const int mt = uid & 31, b = (uid >> 5) & 1, np = uid >> 6;

        if (t < 128) sBest[t] = 0ULL;
        {   // W2 splits (64KB) -> smem
            const uint4* src = (const uint4*)(g_w2split + (size_t)mt * 2 * SPLIT_BYTES);
            uint4* dst = (uint4*)(smc + SM_W2);
#pragma unroll
            for (int i = 0; i < 8; i++) dst[t + 512 * i] = src[t + 512 * i];
        }
        __syncthreads();

        const unsigned char* fsrc = g_fsplit + ((size_t)(b * NTILES + np * NCHUNKS) * 2) * SPLIT_BYTES;
        {   // prologue: chunk 0 -> buf 0
            uint32_t d = smem_base + SM_F + t * 16;
            const unsigned char* sp = fsrc + t * 16;
#pragma unroll
            for (int i = 0; i < 8; i++) cp16(d + i * 8192, sp + i * 8192);
            CP_COMMIT();
        }

        float acc[2][4][4];
#pragma unroll
        for (int mi = 0; mi < 2; mi++)
#pragma unroll
            for (int ni = 0; ni < 4; ni++)
#pragma unroll
                for (int q = 0; q < 4; q++) acc[mi][ni][q] = 0.0f;
        float bv[4]; int bn[4];
#pragma unroll
        for (int q = 0; q < 4; q++) { bv[q] = -1e38f; bn[q] = 0; }

        const float* u_unit = u + (size_t)b * NPTS * MPTS
                            + ((size_t)np * NPART + wn * 32 + 2 * (lane & 3)) * MPTS
                            + (mt * 128 + wm * 32 + (lane >> 2));
        const int n_unit = np * NPART + wn * 32 + 2 * (lane & 3);

        for (int c = 0; c < NCHUNKS; c++) {
            const int buf = c & 1;
            CP_WAIT0();
            __syncthreads();
            if (c + 1 < NCHUNKS) {
                uint32_t d = smem_base + SM_F + (buf ^ 1) * CHUNK_BYTES + t * 16;
                const unsigned char* sp = fsrc + (size_t)(c + 1) * CHUNK_BYTES + t * 16;
#pragma unroll
                for (int i = 0; i < 8; i++) cp16(d + i * 8192, sp + i * 8192);
            }
            CP_COMMIT();

            const uint32_t fa0 = smem_base + SM_F + buf * CHUNK_BYTES;   // f_a tiles
            const uint32_t fb1 = fa0 + SPLIT_BYTES;                      // f_b tiles

            // ---- product block 1: f_a x {w_a, w_b} (128 mma) ----
#pragma unroll
            for (int kh = 0; kh < 2; kh++) {
                const uint32_t fhb = fa0 + kh * TILE_BYTES;
                const uint32_t whb = smem_base + SM_W2 + kh * TILE_BYTES;
#pragma unroll
                for (int ks = 0; ks < 4; ks++) {
                    uint32_t bf0[4], bf1[4];
                    ldsm_x4(bf0, fhb + SW128(b_row + ks * 32));
                    ldsm_x4(bf1, fhb + SW128(b_row + 2048 + ks * 32));
#pragma unroll
                    for (int sw = 0; sw < 2; sw++)
#pragma unroll
                        for (int mi = 0; mi < 2; mi++) {
                            uint32_t af[4];
                            ldsm_x4(af, whb + sw * SPLIT_BYTES + SW128(a_row + mi * 2048 + ks * 32));
                            mma16816(acc[mi][0], af, bf0);
                            mma16816(acc[mi][1], af, bf0 + 2);
                            mma16816(acc[mi][2], af, bf1);
                            mma16816(acc[mi][3], af, bf1 + 2);
                        }
                }
            }

            // ---- u prefetch (32 LDG) — latency hides under product block 2 ----
            const float* uc = u_unit + (size_t)(c * 128) * MPTS;
            float uu[32];
#pragma unroll
            for (int mi = 0; mi < 2; mi++)
#pragma unroll
                for (int hh = 0; hh < 2; hh++)
#pragma unroll
                    for (int ni = 0; ni < 4; ni++)
#pragma unroll
                        for (int j = 0; j < 2; j++)
                            uu[mi * 16 + hh * 8 + ni * 2 + j] =
                                __ldg(uc + (size_t)(ni * 8 + j) * MPTS + mi * 16 + hh * 8);

            // ---- product block 2: f_b x w_a (64 mma) ----
#pragma unroll
            for (int kh = 0; kh < 2; kh++) {
                const uint32_t fhb = fb1 + kh * TILE_BYTES;
                const uint32_t whb = smem_base + SM_W2 + kh * TILE_BYTES;
#pragma unroll
                for (int ks = 0; ks < 4; ks++) {
                    uint32_t bf0[4], bf1[4];
                    ldsm_x4(bf0, fhb + SW128(b_row + ks * 32));
                    ldsm_x4(bf1, fhb + SW128(b_row + 2048 + ks * 32));
#pragma unroll
                    for (int mi = 0; mi < 2; mi++) {
                        uint32_t af[4];
                        ldsm_x4(af, whb + SW128(a_row + mi * 2048 + ks * 32));
                        mma16816(acc[mi][0], af, bf0);
                        mma16816(acc[mi][1], af, bf0 + 2);
                        mma16816(acc[mi][2], af, bf1);
                        mma16816(acc[mi][3], af, bf1 + 2);
                    }
                }
            }

            // ---- epilogue: gumbel + argmax over the chunk ----
            const int n0 = n_unit + c * 128;
#pragma unroll
            for (int mi = 0; mi < 2; mi++)
#pragma unroll
                for (int hh = 0; hh < 2; hh++) {
                    const int slot = mi * 2 + hh;
                    float lbv = bv[slot]; int lbn = bn[slot];
#pragma unroll
                    for (int ni = 0; ni < 4; ni++)
#pragma unroll
                        for (int j = 0; j < 2; j++) {
                            float val = acc[mi][ni][hh * 2 + j];
                            float t1 = fast_nlog(uu[mi * 16 + hh * 8 + ni * 2 + j] + EPSF);
                            float g  = fast_nlog(t1 + EPSF);
                            float sc = fmaf(val, 0.015625f, g);   // /64 W2 scale
                            if (sc > lbv) { lbv = sc; lbn = n0 + ni * 8 + j; }
                            acc[mi][ni][hh * 2 + j] = 0.0f;
                        }
                    bv[slot] = lbv; bn[slot] = lbn;
                }
        }

        // flush unit results
#pragma unroll
        for (int mi = 0; mi < 2; mi++)
#pragma unroll
            for (int hh = 0; hh < 2; hh++) {
                const int slot = mi * 2 + hh;
                unsigned long long key = ((unsigned long long)enc_f(bv[slot]) << 32)
                                       | (0xFFFFFFFFu - (uint32_t)bn[slot]);
                atomicMax(&sBest[wm * 32 + mi * 16 + hh * 8 + (lane >> 2)], key);
            }
        __syncthreads();
        if (t < 128) atomicMax(&g_best[(size_t)b * MPTS + mt * 128 + t], sBest[t]);
        __syncthreads();
    }
}

// ---------------- kernel C: decode idx, write xyz + indices ----------------
__global__ void k_pick(const float* __restrict__ xyzs, float* __restrict__ out) {
    int i = blockIdx.x * blockDim.x + threadIdx.x;
    if (i >= NB * MPTS) return;
    int b = i / MPTS;
    unsigned long long key = g_best[i];
    int n = (int)(0xFFFFFFFFu - (unsigned int)(key & 0xFFFFFFFFull));
    g_idx[i] = n;
    const float* x = xyzs + ((size_t)b * NPTS + n) * 3;
    out[XYZ_OFF + 3 * i + 0] = x[0];
    out[XYZ_OFF + 3 * i + 1] = x[1];
    out[XYZ_OFF + 3 * i + 2] = x[2];
    out[IDX_OFF + i] = (float)n;
}

// ---------------- kernel D: gather features (b, Cout, M) from fp16 splits ----
__global__ void k_gather(float* __restrict__ out) {
    int j = blockIdx.x * blockDim.x + threadIdx.x;
    if (j >= NB * COUT * MPTS) return;
    int b = j / (COUT * MPTS);
    int d = (j / MPTS) % COUT;
    int m = j % MPTS;
    int n = g_idx[b * MPTS + m];
    const unsigned char* tb = g_fsplit + ((size_t)(b * NTILES + (n >> 7)) * 2) * SPLIT_BYTES
                            + (d >> 6) * TILE_BYTES;
    uint32_t off = SW128((uint32_t)((n & 127) * 128 + (d & 63) * 2));
    float fa = __half2float(*(const __half*)(tb + off));
    float fb = __half2float(*(const __half*)(tb + SPLIT_BYTES + off));
    out[FEAT_OFF + j] = fa + fb;
}

// ---------------- launch ----------------
extern "C" void kernel_launch(void* const* d_in, const int* in_sizes, int n_in,
                              void* d_out, int out_size) {
    const float* xyzs  = (const float*)d_in[0];
    const float* feats = (const float*)d_in[1];
    const float* u     = (const float*)d_in[2];
    const float* W1    = (const float*)d_in[3];
    const float* b1    = (const float*)d_in[4];
    const float* W2    = (const float*)d_in[5];
    // d_in[6] = b2: constant per m-column -> cannot change the argmax; unused.
    float* out = (float*)d_out;

    const int smemA = (64 * 132 + 64 * 128) * 4;
    cudaFuncSetAttribute(k_feat, cudaFuncAttributeMaxDynamicSharedMemorySize, smemA);
    cudaFuncSetAttribute(k_main, cudaFuncAttributeMaxDynamicSharedMemorySize, SM_TOT);

    k_w2split<<<MTILES, 128>>>(W2);
    k_feat<<<dim3(NTILES, NB), 256, smemA>>>(feats, W1, b1);
    k_main<<<NCTA, 512, SM_TOT>>>(u);
    k_pick<<<(NB * MPTS + 255) / 256, 256>>>(xyzs, out);
    k_gather<<<(NB * COUT * MPTS + 255) / 256, 256>>>(out);
}